// round 2
// baseline (speedup 1.0000x reference)
#include <cuda_runtime.h>
#include <cstdint>

// Problem constants
#define NQ   8
#define BINS 1024
#define DIM  256
#define BB   8
#define TT   8192
#define NTOK (BB * TT)          // 65536 tokens
#define MT   128                // tokens per block
#define NBLK (NTOK / MT)        // 512 blocks
#define NC   128                // j-chunk width
#define KSL  32                 // K slice
#define RS   132                // Rsm row stride (floats), padded vs 128
#define QOFF 16777216           // quantized elements
#define CELEMS (NQ * BB * TT)   // 524288 codes
#define COFF (QOFF + CELEMS)    // scalar offset

// Shared memory layout (floats)
#define SM_R    0                       // 256*132 = 33792
#define SM_C    (256 * RS)              // 2*32*128 = 8192
#define SM_REDV (SM_C + 2 * KSL * NC)   // 128*16 = 2048
#define SM_REDI (SM_REDV + MT * 16)     // 128*16 = 2048 (int)
#define SM_SIDX (SM_REDI + MT * 16)     // 128 (int)
#define SM_SSQ  (SM_SIDX + MT)          // 256
#define SM_TOTAL_FLOATS (SM_SSQ + 256)
#define SM_BYTES (SM_TOTAL_FLOATS * 4)  // 185856 bytes

__device__ float g_cbsq[NQ * BINS];
__device__ float g_ssq[NQ * NBLK];

// ---------------------------------------------------------------------------
// Kernel 1: per-codeword squared norms
// ---------------------------------------------------------------------------
__global__ void rvq_cbsq_kernel(const float* __restrict__ cbs) {
    int id = blockIdx.x * blockDim.x + threadIdx.x;
    if (id >= NQ * BINS) return;
    const float* c = cbs + (size_t)id * DIM;
    float s0 = 0.f, s1 = 0.f, s2 = 0.f, s3 = 0.f;
    #pragma unroll 8
    for (int d = 0; d < DIM; d += 4) {
        float4 v = *(const float4*)(c + d);
        s0 = fmaf(v.x, v.x, s0);
        s1 = fmaf(v.y, v.y, s1);
        s2 = fmaf(v.z, v.z, s2);
        s3 = fmaf(v.w, v.w, s3);
    }
    g_cbsq[id] = (s0 + s1) + (s2 + s3);
}

// ---------------------------------------------------------------------------
// Kernel 2: main RVQ — residual tile resident in SMEM across all 8 steps
// ---------------------------------------------------------------------------
__global__ __launch_bounds__(256, 1)
void rvq_main_kernel(const float* __restrict__ x,
                     const float* __restrict__ cbs,
                     float* __restrict__ out) {
    extern __shared__ float sm[];
    float* Rsm  = sm + SM_R;              // [256 k][RS] (k-major, m inner)
    float* Csm  = sm + SM_C;              // 2 buffers of [32 kk][128 j]
    float* redv = sm + SM_REDV;           // [128 m][16]
    int*   redi = (int*)(sm + SM_REDI);   // [128 m][16]
    int*   sidx = (int*)(sm + SM_SIDX);   // [128]
    float* ssqs = sm + SM_SSQ;            // [256]

    const int tid = threadIdx.x;
    const int bid = blockIdx.x;
    const int b   = bid >> 6;             // 64 tiles per batch row
    const int t0  = (bid & 63) << 7;
    const float* xblk = x + ((size_t)b * DIM) * TT + t0;

    // Load x tile: Rsm[d][m] = x[b][d][t0+m]  (coalesced over m)
    for (int i = tid; i < DIM * MT; i += 256) {
        int d = i >> 7, m = i & 127;
        Rsm[d * RS + m] = xblk[(size_t)d * TT + m];
    }
    __syncthreads();

    // GEMM thread mapping: 8 warps = 4 (m) x 2 (j); lane = 4 (mi) x 8 (ji)
    const int lane = tid & 31, warp = tid >> 5;
    const int mi = lane & 3, ji = lane >> 2;
    const int tm = (warp & 3) * 4 + mi;   // 0..15 -> tokens tm*8..+7
    const int tj = (warp >> 2) * 8 + ji;  // 0..15 -> j offs tj*8..+7
    const int aoff = tm * 8;
    const int boff = tj * 8;

    // Loader mapping for C slices
    const int lj = tid >> 3;              // 0..31 row-in-group
    const int lg = tid & 7;               // 0..7 -> float4 column

    for (int q = 0; q < NQ; ++q) {
        const float* cb   = cbs + (size_t)q * BINS * DIM;
        const float* cbsq = g_cbsq + q * BINS;

        float best[8];
        int   bidx[8];
        #pragma unroll
        for (int im = 0; im < 8; ++im) { best[im] = 3.4e38f; bidx[im] = 0; }

        for (int jc = 0; jc < BINS / NC; ++jc) {  // 8 chunks, ascending j
            const int j0 = jc * NC;
            float acc[8][8];
            #pragma unroll
            for (int im = 0; im < 8; ++im)
                #pragma unroll
                for (int ij = 0; ij < 8; ++ij) acc[im][ij] = 0.f;

            // Preload slice 0 into buffer 0 (transpose to [kk][j])
            {
                const float* src = cb + (size_t)(j0 + lj) * DIM + lg * 4;
                #pragma unroll
                for (int p = 0; p < 4; ++p) {
                    float4 v = *(const float4*)(src + (size_t)(p * 32) * DIM);
                    int row = p * 32 + lj;
                    Csm[(lg * 4 + 0) * NC + row] = v.x;
                    Csm[(lg * 4 + 1) * NC + row] = v.y;
                    Csm[(lg * 4 + 2) * NC + row] = v.z;
                    Csm[(lg * 4 + 3) * NC + row] = v.w;
                }
            }
            __syncthreads();

            for (int s = 0; s < DIM / KSL; ++s) {   // 8 K-slices
                float4 n0, n1, n2, n3;
                if (s < 7) {
                    const float* src = cb + (size_t)(j0 + lj) * DIM + (s + 1) * KSL + lg * 4;
                    n0 = *(const float4*)(src + (size_t)(0 * 32) * DIM);
                    n1 = *(const float4*)(src + (size_t)(1 * 32) * DIM);
                    n2 = *(const float4*)(src + (size_t)(2 * 32) * DIM);
                    n3 = *(const float4*)(src + (size_t)(3 * 32) * DIM);
                }
                const float* Cb = Csm + (s & 1) * (KSL * NC);
                const float* Rb = Rsm + s * KSL * RS;
                #pragma unroll 8
                for (int kk = 0; kk < KSL; ++kk) {
                    float4 a0 = *(const float4*)(Rb + kk * RS + aoff);
                    float4 a1 = *(const float4*)(Rb + kk * RS + aoff + 4);
                    float4 b0 = *(const float4*)(Cb + kk * NC + boff);
                    float4 b1 = *(const float4*)(Cb + kk * NC + boff + 4);
                    float av[8] = {a0.x, a0.y, a0.z, a0.w, a1.x, a1.y, a1.z, a1.w};
                    float bv[8] = {b0.x, b0.y, b0.z, b0.w, b1.x, b1.y, b1.z, b1.w};
                    #pragma unroll
                    for (int im = 0; im < 8; ++im)
                        #pragma unroll
                        for (int ij = 0; ij < 8; ++ij)
                            acc[im][ij] = fmaf(av[im], bv[ij], acc[im][ij]);
                }
                if (s < 7) {
                    float* dst = Csm + ((s + 1) & 1) * (KSL * NC);
                    #pragma unroll
                    for (int p = 0; p < 4; ++p) {
                        int row = p * 32 + lj;
                        float4 v = (p == 0) ? n0 : (p == 1) ? n1 : (p == 2) ? n2 : n3;
                        dst[(lg * 4 + 0) * NC + row] = v.x;
                        dst[(lg * 4 + 1) * NC + row] = v.y;
                        dst[(lg * 4 + 2) * NC + row] = v.z;
                        dst[(lg * 4 + 3) * NC + row] = v.w;
                    }
                }
                __syncthreads();
            }

            // Epilogue: dist = cb_sq[j] - 2*dot ; running argmin (j ascending)
            #pragma unroll
            for (int ij = 0; ij < 8; ++ij) {
                int j = j0 + boff + ij;
                float cq = cbsq[j];
                #pragma unroll
                for (int im = 0; im < 8; ++im) {
                    float dist = cq - 2.0f * acc[im][ij];
                    if (dist < best[im]) { best[im] = dist; bidx[im] = j; }
                }
            }
        }

        // Cross-thread argmin reduction per token (16 tj-partials each)
        #pragma unroll
        for (int im = 0; im < 8; ++im) {
            redv[(aoff + im) * 16 + tj] = best[im];
            redi[(aoff + im) * 16 + tj] = bidx[im];
        }
        __syncthreads();
        if (tid < MT) {
            float bv = redv[tid * 16];
            int   bi = redi[tid * 16];
            #pragma unroll
            for (int r = 1; r < 16; ++r) {
                float v = redv[tid * 16 + r];
                int   ix = redi[tid * 16 + r];
                if (v < bv || (v == bv && ix < bi)) { bv = v; bi = ix; }
            }
            sidx[tid] = bi;
            // codes[q][b][t0+tid] as float
            out[QOFF + ((size_t)(q * BB + b)) * TT + t0 + tid] = (float)bi;
        }
        __syncthreads();

        // Residual update: r[d][m] -= cb[idx[m]][d]; accumulate new ssq.
        // tid == d (0..255); coalesced codeword row gathers.
        float ssql = 0.f;
        #pragma unroll 4
        for (int m = 0; m < MT; ++m) {
            int ix = sidx[m];
            float c = __ldg(cb + (size_t)ix * DIM + tid);
            float r = Rsm[tid * RS + m] - c;
            Rsm[tid * RS + m] = r;
            ssql = fmaf(r, r, ssql);
        }
        ssqs[tid] = ssql;
        __syncthreads();
        if (tid == 0) {
            float s = 0.f;
            for (int i = 0; i < 256; ++i) s += ssqs[i];
            g_ssq[q * NBLK + bid] = s;
        }
        __syncthreads();
    }

    // quantized = x - r_final, written back in [B][D][T] layout (coalesced)
    for (int i = tid; i < DIM * MT; i += 256) {
        int d = i >> 7, m = i & 127;
        out[((size_t)b * DIM + d) * TT + t0 + m] =
            xblk[(size_t)d * TT + m] - Rsm[d * RS + m];
    }
}

// ---------------------------------------------------------------------------
// Kernel 3: finalize scalars (deterministic fixed-order reduction)
// ---------------------------------------------------------------------------
__global__ void rvq_finalize_kernel(const int* __restrict__ sr_raw,
                                    float* __restrict__ out) {
    if (threadIdx.x != 0 || blockIdx.x != 0) return;
    float total = 0.f;
    for (int q = 0; q < NQ; ++q) {
        float s = 0.f;
        for (int i = 0; i < NBLK; ++i) s += g_ssq[q * NBLK + i];
        total += 0.25f * (s / (float)(NTOK * DIM));
    }
    // sample_rate: int32 expected; fall back to float bit-pattern heuristic
    int   iv = sr_raw[0];
    float sr;
    if (iv > 0 && iv < 100000000) sr = (float)iv;
    else                          sr = __int_as_float(iv);
    out[COFF + 0] = (float)NQ * 10.0f * (sr / 1000.0f);  // log2(1024)=10
    out[COFF + 1] = total / (float)NQ;
}

// ---------------------------------------------------------------------------
extern "C" void kernel_launch(void* const* d_in, const int* in_sizes, int n_in,
                              void* d_out, int out_size) {
    const float* x   = (const float*)d_in[0];
    const int*   sr  = (const int*)d_in[1];
    const float* cbs = (const float*)d_in[2];
    float* out = (float*)d_out;

    cudaFuncSetAttribute(rvq_main_kernel,
                         cudaFuncAttributeMaxDynamicSharedMemorySize, SM_BYTES);

    rvq_cbsq_kernel<<<(NQ * BINS + 255) / 256, 256>>>(cbs);
    rvq_main_kernel<<<NBLK, 256, SM_BYTES>>>(x, cbs, out);
    rvq_finalize_kernel<<<1, 32>>>(sr, out);
}

// round 6
// speedup vs baseline: 2.1887x; 2.1887x over previous
#include <cuda_runtime.h>
#include <cuda_fp16.h>
#include <cstdint>

#define NQ 8
#define BINS 1024
#define DIM 256
#define BB 8
#define TT 8192
#define NTOK (BB*TT)            // 65536
#define MT 128
#define NBLK (NTOK/MT)          // 512
#define QOFF 16777216
#define COFF (QOFF + NQ*NTOK)
#define INV2048 4.8828125e-4f

#define ASTR_H 264              // A row stride in halfs (528 B)
#define ASTR_B 528
#define A_BYTES (128*ASTR_B)    // 67584
#define BROW_B 528
#define BHALF 16896             // 32 rows * 528
#define BBUF  33792             // hi + lo

#define SO_CBSQ 0
#define SO_SIDX 4096
#define SO_SSQ  4608
#define SO_AHI  8192
#define SO_ALO  (SO_AHI + A_BYTES)   // 75776
#define SO_B    (SO_ALO + A_BYTES)   // 143360
#define SMEM_BYTES (SO_B + 2*BBUF)   // 210944

__device__ __half g_bhi[(size_t)NQ*BINS*DIM];   // 4MB
__device__ __half g_blo[(size_t)NQ*BINS*DIM];   // 4MB
__device__ float g_cbsq[NQ*BINS];
__device__ float g_ssq[NQ*NBLK];

static __device__ __forceinline__ uint32_t smem_u32(const void* p){
    uint32_t a;
    asm("{ .reg .u64 t; cvta.to.shared.u64 t, %1; cvt.u32.u64 %0, t; }":"=r"(a):"l"(p));
    return a;
}
static __device__ __forceinline__ void split2(float v, __half& hi, __half& lo){
    hi = __float2half_rn(v);
    lo = __float2half_rn((v - __half2float(hi)) * 2048.0f);
}
static __device__ __forceinline__ void cpasync16(uint32_t s, const void* g){
    asm volatile("cp.async.cg.shared.global [%0], [%1], 16;"::"r"(s),"l"(g):"memory");
}
#define CP_COMMIT() asm volatile("cp.async.commit_group;":::"memory")
#define CP_WAIT1()  asm volatile("cp.async.wait_group 1;":::"memory")
#define CP_WAIT0()  asm volatile("cp.async.wait_group 0;":::"memory")

static __device__ __forceinline__ void ldsm4(uint32_t* r, uint32_t a){
    asm volatile("ldmatrix.sync.aligned.m8n8.x4.shared.b16 {%0,%1,%2,%3}, [%4];"
        :"=r"(r[0]),"=r"(r[1]),"=r"(r[2]),"=r"(r[3]):"r"(a));
}
static __device__ __forceinline__ void mma16816(float* c, const uint32_t* a,
                                                uint32_t b0, uint32_t b1){
    asm volatile("mma.sync.aligned.m16n8k16.row.col.f32.f16.f16.f32 "
        "{%0,%1,%2,%3}, {%4,%5,%6,%7}, {%8,%9}, {%0,%1,%2,%3};"
        : "+f"(c[0]),"+f"(c[1]),"+f"(c[2]),"+f"(c[3])
        : "r"(a[0]),"r"(a[1]),"r"(a[2]),"r"(a[3]),"r"(b0),"r"(b1));
}

// ---------------- prep: split codebooks into fp16 hi/lo images ----------------
__global__ void rvq_prep_kernel(const float* __restrict__ cbs){
    int id = blockIdx.x*blockDim.x + threadIdx.x;
    if (id >= NQ*BINS*DIM) return;
    __half hi, lo; split2(cbs[id], hi, lo);
    g_bhi[id] = hi; g_blo[id] = lo;
}

__global__ void rvq_cbsq_kernel(const float* __restrict__ cbs){
    int id = blockIdx.x*blockDim.x + threadIdx.x;
    if (id >= NQ*BINS) return;
    const float* c = cbs + (size_t)id*DIM;
    float s0=0,s1=0,s2=0,s3=0;
    #pragma unroll 8
    for (int d=0; d<DIM; d+=4){
        float4 v = *(const float4*)(c+d);
        s0=fmaf(v.x,v.x,s0); s1=fmaf(v.y,v.y,s1); s2=fmaf(v.z,v.z,s2); s3=fmaf(v.w,v.w,s3);
    }
    g_cbsq[id] = (s0+s1)+(s2+s3);
}

// ---------------- main ----------------
__global__ __launch_bounds__(256,1)
void rvq_main_kernel(const float* __restrict__ x, const float* __restrict__ cbs,
                     float* __restrict__ out){
    extern __shared__ char smc[];
    const uint32_t sb = smem_u32(smc);
    const int tid = threadIdx.x, l = tid&31, w = tid>>5, bid = blockIdx.x;
    const int b = bid>>6, t0 = (bid&63)<<7;
    const float* xblk = x + ((size_t)b*DIM)*TT + t0;
    float* cbsq_s = (float*)(smc+SO_CBSQ);
    int*   sidx   = (int*)(smc+SO_SIDX);
    float* ssqs   = (float*)(smc+SO_SSQ);
    __half* pH = (__half*)(smc+SO_AHI);
    __half* pL = (__half*)(smc+SO_ALO);

    // initial residual = x (split fp16 hi/lo, [m][d] layout)
    for (int i=tid; i<DIM*MT; i+=256){
        int d = i>>7, m = i&127;
        __half hi, lo; split2(xblk[(size_t)d*TT+m], hi, lo);
        int o = m*ASTR_H + d;
        pH[o] = hi; pL[o] = lo;
    }
    __syncthreads();

    // per-lane ldmatrix addresses
    const uint32_t aW = sb + SO_AHI + (w*16 + (l&15))*ASTR_B + (l>>4)*16;
    const uint32_t bLane = (uint32_t)(((l&7) | ((l&16)>>1))*BROW_B + ((l>>3)&1)*16);

    for (int q=0; q<NQ; ++q){
        const float* cbq = cbs + (size_t)q*BINS*DIM;
        for (int i=tid; i<BINS; i+=256) cbsq_s[i] = g_cbsq[q*BINS+i];

        // prefetch chunk 0
        {
            size_t gb = (size_t)q*BINS*DIM;
            #pragma unroll
            for (int h=0; h<2; ++h){
                const __half* src = (h? g_blo : g_bhi) + gb;
                uint32_t dst = sb + SO_B + h*BHALF;
                #pragma unroll
                for (int i=0;i<4;++i){
                    int e = tid + i*256, row = e>>5, ch = e&31;
                    cpasync16(dst + row*BROW_B + ch*16, src + row*DIM + ch*8);
                }
            }
            CP_COMMIT();
        }

        float best0 = 3.4e38f, best1 = 3.4e38f;
        int bi0 = 0, bi1 = 0;

        for (int c=0; c<32; ++c){
            if (c < 31){
                size_t gb = ((size_t)q*BINS + (size_t)(c+1)*32)*DIM;
                int s2 = (c+1)&1;
                #pragma unroll
                for (int h=0; h<2; ++h){
                    const __half* src = (h? g_blo : g_bhi) + gb;
                    uint32_t dst = sb + SO_B + s2*BBUF + h*BHALF;
                    #pragma unroll
                    for (int i=0;i<4;++i){
                        int e = tid + i*256, row = e>>5, ch = e&31;
                        cpasync16(dst + row*BROW_B + ch*16, src + row*DIM + ch*8);
                    }
                }
                CP_COMMIT();
                CP_WAIT1();
            } else {
                CP_WAIT0();
            }
            __syncthreads();

            // GEMM on buffer c&1
            float acc1[4][4], acc2[4][4];
            #pragma unroll
            for (int t=0;t<4;++t)
                #pragma unroll
                for (int i=0;i<4;++i){ acc1[t][i]=0.f; acc2[t][i]=0.f; }

            const uint32_t bbuf = sb + SO_B + (c&1)*BBUF + bLane;
            #pragma unroll 4
            for (int kt=0; kt<16; ++kt){
                uint32_t ah[4], al[4];
                ldsm4(ah, aW + kt*32);
                ldsm4(al, aW + A_BYTES + kt*32);
                #pragma unroll
                for (int g=0; g<2; ++g){
                    uint32_t bh[4], bl[4];
                    uint32_t ba = bbuf + g*8448 + kt*32;
                    ldsm4(bh, ba);
                    ldsm4(bl, ba + BHALF);
                    mma16816(acc1[g*2],   ah, bh[0], bh[1]);
                    mma16816(acc1[g*2+1], ah, bh[2], bh[3]);
                    mma16816(acc2[g*2],   ah, bl[0], bl[1]);
                    mma16816(acc2[g*2+1], ah, bl[2], bl[3]);
                    mma16816(acc2[g*2],   al, bh[0], bh[1]);
                    mma16816(acc2[g*2+1], al, bh[2], bh[3]);
                }
            }

            // distances + running argmin (ascending j)
            #pragma unroll
            for (int t=0;t<4;++t){
                int n = c*32 + t*8 + (l&3)*2;
                float cq0 = cbsq_s[n], cq1 = cbsq_s[n+1];
                float d00 = cq0 - 2.f*fmaf(acc2[t][0], INV2048, acc1[t][0]);
                float d01 = cq1 - 2.f*fmaf(acc2[t][1], INV2048, acc1[t][1]);
                float d10 = cq0 - 2.f*fmaf(acc2[t][2], INV2048, acc1[t][2]);
                float d11 = cq1 - 2.f*fmaf(acc2[t][3], INV2048, acc1[t][3]);
                if (d00 < best0){ best0=d00; bi0=n; }
                if (d01 < best0){ best0=d01; bi0=n+1; }
                if (d10 < best1){ best1=d10; bi1=n; }
                if (d11 < best1){ best1=d11; bi1=n+1; }
            }
            __syncthreads();
        }

        // reduce argmin across the 4 lanes sharing each row
        #pragma unroll
        for (int o=1;o<=2;o<<=1){
            float v0=__shfl_xor_sync(0xFFFFFFFFu,best0,o);
            int   i0=__shfl_xor_sync(0xFFFFFFFFu,bi0,o);
            if (v0<best0 || (v0==best0 && i0<bi0)){ best0=v0; bi0=i0; }
            float v1=__shfl_xor_sync(0xFFFFFFFFu,best1,o);
            int   i1=__shfl_xor_sync(0xFFFFFFFFu,bi1,o);
            if (v1<best1 || (v1==best1 && i1<bi1)){ best1=v1; bi1=i1; }
        }
        if ((l&3)==0){
            int r = l>>2;
            sidx[w*16+r]   = bi0;
            sidx[w*16+r+8] = bi1;
            size_t cbase = (size_t)QOFF + ((size_t)(q*BB+b))*TT + t0 + w*16;
            out[cbase + r]     = (float)bi0;
            out[cbase + r + 8] = (float)bi1;
        }
        __syncthreads();

        // residual update (tid = dim d), reconstruct-subtract-resplit
        {
            float ssq = 0.f;
            #pragma unroll 4
            for (int m=0; m<MT; ++m){
                int ix = sidx[m];
                float cv = __ldg(cbq + (size_t)ix*DIM + tid);
                int o = m*ASTR_H + tid;
                float r = __half2float(pH[o]) + __half2float(pL[o])*INV2048;
                float rn = r - cv;
                __half hi, lo; split2(rn, hi, lo);
                pH[o]=hi; pL[o]=lo;
                ssq = fmaf(rn, rn, ssq);
            }
            #pragma unroll
            for (int o=16;o>0;o>>=1) ssq += __shfl_xor_sync(0xFFFFFFFFu, ssq, o);
            if (l==0) ssqs[w] = ssq;
            __syncthreads();
            if (tid==0){
                float s=0.f;
                #pragma unroll
                for (int ww=0; ww<8; ++ww) s += ssqs[ww];
                g_ssq[q*NBLK+bid] = s;
            }
            __syncthreads();
        }
    }

    // quantized = x - r_final
    for (int i=tid; i<DIM*MT; i+=256){
        int d = i>>7, m = i&127;
        int o = m*ASTR_H + d;
        float r = __half2float(pH[o]) + __half2float(pL[o])*INV2048;
        out[((size_t)b*DIM+d)*TT + t0 + m] = xblk[(size_t)d*TT+m] - r;
    }
}

__global__ void rvq_finalize_kernel(const int* __restrict__ sr_raw, float* __restrict__ out){
    if (threadIdx.x != 0 || blockIdx.x != 0) return;
    float total = 0.f;
    for (int q=0; q<NQ; ++q){
        float s = 0.f;
        for (int i=0; i<NBLK; ++i) s += g_ssq[q*NBLK+i];
        total += 0.25f * (s / (float)((size_t)NTOK*DIM));
    }
    int iv = sr_raw[0];
    float sr = (iv > 0 && iv < 100000000) ? (float)iv : __int_as_float(iv);
    out[COFF+0] = (float)NQ * 10.0f * (sr / 1000.0f);
    out[COFF+1] = total / (float)NQ;
}

extern "C" void kernel_launch(void* const* d_in, const int* in_sizes, int n_in,
                              void* d_out, int out_size){
    const float* x   = (const float*)d_in[0];
    const int*   sr  = (const int*)d_in[1];
    const float* cbs = (const float*)d_in[2];
    float* out = (float*)d_out;
    cudaFuncSetAttribute(rvq_main_kernel, cudaFuncAttributeMaxDynamicSharedMemorySize, SMEM_BYTES);
    rvq_prep_kernel<<<(NQ*BINS*DIM+255)/256, 256>>>(cbs);
    rvq_cbsq_kernel<<<(NQ*BINS+255)/256, 256>>>(cbs);
    rvq_main_kernel<<<NBLK, 256, SMEM_BYTES>>>(x, cbs, out);
    rvq_finalize_kernel<<<1, 32>>>(sr, out);
}

// round 8
// speedup vs baseline: 2.4117x; 1.1019x over previous
#include <cuda_runtime.h>
#include <cuda_fp16.h>
#include <cstdint>

#define NQ 8
#define BINS 1024
#define DIM 256
#define BB 8
#define TT 8192
#define NTOK (BB*TT)            // 65536
#define MT 128
#define NBLK (NTOK/MT)          // 512
#define QOFF 16777216
#define COFF (QOFF + NQ*NTOK)
#define INV2048 4.8828125e-4f

#define ASTR_H 264              // A row stride in halfs (528 B)
#define ASTR_B 528
#define A_BYTES (128*ASTR_B)    // 67584
#define CHUNK_B 32768           // one B chunk: [hi 16KB][lo 16KB], rows 512B swizzled

#define SO_CBSQ 0
#define SO_SIDX 4096
#define SO_SSQ  4608
#define SO_MBAR 4672            // 2 mbarriers
#define SO_AHI  8192
#define SO_ALO  (SO_AHI + A_BYTES)   // 75776
#define SO_B    (SO_ALO + A_BYTES)   // 143360
#define SMEM_BYTES (SO_B + 2*CHUNK_B) // 208896

__device__ __align__(128) unsigned char g_bimg[(size_t)NQ*32*CHUNK_B]; // 8MB
__device__ float g_cbsq[NQ*BINS];
__device__ float g_ssq[NQ*NBLK];

static __device__ __forceinline__ uint32_t smem_u32(const void* p){
    uint32_t a;
    asm("{ .reg .u64 t; cvta.to.shared.u64 t, %1; cvt.u32.u64 %0, t; }":"=r"(a):"l"(p));
    return a;
}
static __device__ __forceinline__ void split2(float v, __half& hi, __half& lo){
    hi = __float2half_rn(v);
    lo = __float2half_rn((v - __half2float(hi)) * 2048.0f);
}
#define MBAR_INIT(a,c) asm volatile("mbarrier.init.shared.b64 [%0], %1;"::"r"(a),"r"(c):"memory")
#define MBAR_EXPECT_TX(a,b) asm volatile("mbarrier.arrive.expect_tx.shared.b64 _, [%0], %1;"::"r"(a),"r"(b):"memory")
static __device__ __forceinline__ void mbar_wait(uint32_t a, uint32_t ph){
    asm volatile("{\n\t.reg .pred P;\nW%=: mbarrier.try_wait.parity.acquire.cta.shared::cta.b64 P, [%0], %1, 0x989680;\n\t@!P bra W%=;\n\t}"
        ::"r"(a),"r"(ph):"memory");
}
static __device__ __forceinline__ void bulkcp(uint32_t dst, const void* src,
                                              uint32_t bytes, uint32_t mb){
    asm volatile("cp.async.bulk.shared::cta.global.mbarrier::complete_tx::bytes [%0], [%1], %2, [%3];"
        ::"r"(dst),"l"(src),"r"(bytes),"r"(mb):"memory");
}
static __device__ __forceinline__ void ldsm4(uint32_t* r, uint32_t a){
    asm volatile("ldmatrix.sync.aligned.m8n8.x4.shared.b16 {%0,%1,%2,%3}, [%4];"
        :"=r"(r[0]),"=r"(r[1]),"=r"(r[2]),"=r"(r[3]):"r"(a));
}
static __device__ __forceinline__ void mma16816(float* c, const uint32_t* a,
                                                uint32_t b0, uint32_t b1){
    asm volatile("mma.sync.aligned.m16n8k16.row.col.f32.f16.f16.f32 "
        "{%0,%1,%2,%3}, {%4,%5,%6,%7}, {%8,%9}, {%0,%1,%2,%3};"
        : "+f"(c[0]),"+f"(c[1]),"+f"(c[2]),"+f"(c[3])
        : "r"(a[0]),"r"(a[1]),"r"(a[2]),"r"(a[3]),"r"(b0),"r"(b1));
}

// ---- prep: split codebooks into pre-swizzled chunk images --------------------
// chunk = 32 bins; layout: [hi|lo], row jr (0..31) at jr*512, 16B-unit u stored
// at unit (u ^ (jr&7))  -> flat bulk-copy target, conflict-free ldmatrix.
__global__ void rvq_prep_kernel(const float* __restrict__ cbs){
    int id = blockIdx.x*blockDim.x + threadIdx.x;
    if (id >= NQ*BINS*DIM) return;
    int d = id & 255, j = (id>>8) & 1023, q = id>>18;
    __half hi, lo; split2(cbs[id], hi, lo);
    int jc = j>>5, jr = j&31;
    uint32_t unit = (uint32_t)(d>>3);
    uint32_t off = (uint32_t)jr*512u + ((unit ^ (uint32_t)(jr&7))<<4) + (uint32_t)(d&7)*2u;
    size_t base = (size_t)(q*32+jc)*CHUNK_B;
    *(__half*)(g_bimg + base + off)         = hi;
    *(__half*)(g_bimg + base + 16384 + off) = lo;
}

__global__ void rvq_cbsq_kernel(const float* __restrict__ cbs){
    int id = blockIdx.x*blockDim.x + threadIdx.x;
    if (id >= NQ*BINS) return;
    const float* c = cbs + (size_t)id*DIM;
    float s0=0,s1=0,s2=0,s3=0;
    #pragma unroll 8
    for (int d=0; d<DIM; d+=4){
        float4 v = *(const float4*)(c+d);
        s0=fmaf(v.x,v.x,s0); s1=fmaf(v.y,v.y,s1); s2=fmaf(v.z,v.z,s2); s3=fmaf(v.w,v.w,s3);
    }
    g_cbsq[id] = (s0+s1)+(s2+s3);
}

// ---- main -------------------------------------------------------------------
__global__ __launch_bounds__(256,1)
void rvq_main_kernel(const float* __restrict__ x, const float* __restrict__ cbs,
                     float* __restrict__ out){
    extern __shared__ char smc[];
    const uint32_t sb = smem_u32(smc);
    const int tid = threadIdx.x, l = tid&31, w = tid>>5, bid = blockIdx.x;
    const int b = bid>>6, t0 = (bid&63)<<7;
    const float* xblk = x + ((size_t)b*DIM)*TT + t0;
    float* cbsq_s = (float*)(smc+SO_CBSQ);
    int*   sidx   = (int*)(smc+SO_SIDX);
    float* ssqs   = (float*)(smc+SO_SSQ);
    __half* pH = (__half*)(smc+SO_AHI);
    __half* pL = (__half*)(smc+SO_ALO);

    if (tid==0){ MBAR_INIT(sb+SO_MBAR,1); MBAR_INIT(sb+SO_MBAR+8,1); }

    // initial residual = x (split fp16 hi/lo, [m][d] layout)
    for (int i=tid; i<DIM*MT; i+=256){
        int d = i>>7, m = i&127;
        __half hi, lo; split2(xblk[(size_t)d*TT+m], hi, lo);
        int o = m*ASTR_H + d;
        pH[o] = hi; pL[o] = lo;
    }
    __syncthreads();

    // per-lane ldmatrix addressing
    const uint32_t aW = sb + SO_AHI + (w*16 + (l&15))*ASTR_B + (l>>4)*16;
    const int nr  = (l&7) | ((l&16)>>1);       // 0..15 n-row within group
    const int suu = (l>>3)&1;                  // k sub-unit (0/1)
    const uint32_t xorv = (uint32_t)(nr&7);
    const uint32_t bRow = sb + SO_B + (uint32_t)nr*512u;

    int ph[2] = {0,0};

    for (int q=0; q<NQ; ++q){
        const float* cbq = cbs + (size_t)q*BINS*DIM;
        for (int i=tid; i<BINS; i+=256) cbsq_s[i] = g_cbsq[q*BINS+i];

        if (tid==0){   // prefetch chunk 0
            MBAR_EXPECT_TX(sb+SO_MBAR, CHUNK_B);
            bulkcp(sb+SO_B, g_bimg + (size_t)(q*32)*CHUNK_B, CHUNK_B, sb+SO_MBAR);
        }

        float best0 = 3.4e38f, best1 = 3.4e38f;
        int bi0 = 0, bi1 = 0;

        for (int c=0; c<32; ++c){
            const int s = c&1;
            if (c < 31 && tid==0){
                const int s2 = (c+1)&1;
                MBAR_EXPECT_TX(sb+SO_MBAR+8*s2, CHUNK_B);
                bulkcp(sb+SO_B+(uint32_t)s2*CHUNK_B,
                       g_bimg + (size_t)(q*32+c+1)*CHUNK_B, CHUNK_B, sb+SO_MBAR+8*s2);
            }
            mbar_wait(sb+SO_MBAR+8*s, ph[s]); ph[s]^=1;

            // GEMM on buffer s
            float acc1[4][4], acc2[4][4];
            #pragma unroll
            for (int t=0;t<4;++t)
                #pragma unroll
                for (int i=0;i<4;++i){ acc1[t][i]=0.f; acc2[t][i]=0.f; }

            const uint32_t bbase = bRow + (uint32_t)s*CHUNK_B;
            #pragma unroll 4
            for (int kt=0; kt<16; ++kt){
                uint32_t ah[4], al[4];
                ldsm4(ah, aW + kt*32);
                ldsm4(al, aW + A_BYTES + kt*32);
                const uint32_t cbyte = ((((uint32_t)(kt*2+suu)) ^ xorv) << 4);
                #pragma unroll
                for (int g=0; g<2; ++g){
                    uint32_t bh[4], bl[4];
                    uint32_t ba = bbase + (uint32_t)g*8192u + cbyte;
                    ldsm4(bh, ba);
                    ldsm4(bl, ba + 16384);
                    mma16816(acc1[g*2],   ah, bh[0], bh[1]);
                    mma16816(acc1[g*2+1], ah, bh[2], bh[3]);
                    mma16816(acc2[g*2],   ah, bl[0], bl[1]);
                    mma16816(acc2[g*2+1], ah, bl[2], bl[3]);
                    mma16816(acc2[g*2],   al, bh[0], bh[1]);
                    mma16816(acc2[g*2+1], al, bh[2], bh[3]);
                }
            }

            // distances + running argmin (ascending j)
            #pragma unroll
            for (int t=0;t<4;++t){
                int n = c*32 + t*8 + (l&3)*2;
                float cq0 = cbsq_s[n], cq1 = cbsq_s[n+1];
                float d00 = cq0 - 2.f*fmaf(acc2[t][0], INV2048, acc1[t][0]);
                float d01 = cq1 - 2.f*fmaf(acc2[t][1], INV2048, acc1[t][1]);
                float d10 = cq0 - 2.f*fmaf(acc2[t][2], INV2048, acc1[t][2]);
                float d11 = cq1 - 2.f*fmaf(acc2[t][3], INV2048, acc1[t][3]);
                if (d00 < best0){ best0=d00; bi0=n; }
                if (d01 < best0){ best0=d01; bi0=n+1; }
                if (d10 < best1){ best1=d10; bi1=n; }
                if (d11 < best1){ best1=d11; bi1=n+1; }
            }
            __syncthreads();   // all warps done with buffer s before refill
        }

        // reduce argmin across the 4 lanes sharing each row
        #pragma unroll
        for (int o=1;o<=2;o<<=1){
            float v0=__shfl_xor_sync(0xFFFFFFFFu,best0,o);
            int   i0=__shfl_xor_sync(0xFFFFFFFFu,bi0,o);
            if (v0<best0 || (v0==best0 && i0<bi0)){ best0=v0; bi0=i0; }
            float v1=__shfl_xor_sync(0xFFFFFFFFu,best1,o);
            int   i1=__shfl_xor_sync(0xFFFFFFFFu,bi1,o);
            if (v1<best1 || (v1==best1 && i1<bi1)){ best1=v1; bi1=i1; }
        }
        if ((l&3)==0){
            int r = l>>2;
            sidx[w*16+r]   = bi0;
            sidx[w*16+r+8] = bi1;
            size_t cbase = (size_t)QOFF + ((size_t)(q*BB+b))*TT + t0 + w*16;
            out[cbase + r]     = (float)bi0;
            out[cbase + r + 8] = (float)bi1;
        }
        __syncthreads();

        // residual update (tid = dim d), reconstruct-subtract-resplit
        {
            float ssq = 0.f;
            #pragma unroll 4
            for (int m=0; m<MT; ++m){
                int ix = sidx[m];
                float cv = __ldg(cbq + (size_t)ix*DIM + tid);
                int o = m*ASTR_H + tid;
                float r = __half2float(pH[o]) + __half2float(pL[o])*INV2048;
                float rn = r - cv;
                __half hi, lo; split2(rn, hi, lo);
                pH[o]=hi; pL[o]=lo;
                ssq = fmaf(rn, rn, ssq);
            }
            #pragma unroll
            for (int o=16;o>0;o>>=1) ssq += __shfl_xor_sync(0xFFFFFFFFu, ssq, o);
            if (l==0) ssqs[w] = ssq;
            __syncthreads();
            if (tid==0){
                float sacc=0.f;
                #pragma unroll
                for (int ww=0; ww<8; ++ww) sacc += ssqs[ww];
                g_ssq[q*NBLK+bid] = sacc;
            }
            __syncthreads();
        }
    }

    // quantized = x - r_final
    for (int i=tid; i<DIM*MT; i+=256){
        int d = i>>7, m = i&127;
        int o = m*ASTR_H + d;
        float r = __half2float(pH[o]) + __half2float(pL[o])*INV2048;
        out[((size_t)b*DIM+d)*TT + t0 + m] = xblk[(size_t)d*TT+m] - r;
    }
}

// ---- finalize: parallel deterministic reduction -----------------------------
__global__ void rvq_finalize_kernel(const int* __restrict__ sr_raw, float* __restrict__ out){
    __shared__ float red[8];
    const int tid = threadIdx.x;
    float s = 0.f;
    #pragma unroll
    for (int i=0; i<NQ*NBLK/256; ++i) s += g_ssq[tid + i*256];
    #pragma unroll
    for (int o=16;o>0;o>>=1) s += __shfl_xor_sync(0xFFFFFFFFu, s, o);
    if ((tid&31)==0) red[tid>>5] = s;
    __syncthreads();
    if (tid==0){
        float tot=0.f;
        #pragma unroll
        for (int w=0; w<8; ++w) tot += red[w];
        int iv = sr_raw[0];
        float sr = (iv > 0 && iv < 100000000) ? (float)iv : __int_as_float(iv);
        out[COFF+0] = (float)NQ * 10.0f * (sr / 1000.0f);
        out[COFF+1] = tot * (0.25f / ((float)((size_t)NTOK*DIM))) / (float)NQ;
    }
}

extern "C" void kernel_launch(void* const* d_in, const int* in_sizes, int n_in,
                              void* d_out, int out_size){
    const float* x   = (const float*)d_in[0];
    const int*   sr  = (const int*)d_in[1];
    const float* cbs = (const float*)d_in[2];
    float* out = (float*)d_out;
    cudaFuncSetAttribute(rvq_main_kernel, cudaFuncAttributeMaxDynamicSharedMemorySize, SMEM_BYTES);
    rvq_prep_kernel<<<(NQ*BINS*DIM+255)/256, 256>>>(cbs);
    rvq_cbsq_kernel<<<(NQ*BINS+255)/256, 256>>>(cbs);
    rvq_main_kernel<<<NBLK, 256, SMEM_BYTES>>>(x, cbs, out);
    rvq_finalize_kernel<<<1, 256>>>(sr, out);
}

// round 10
// speedup vs baseline: 2.5592x; 1.0611x over previous
#include <cuda_runtime.h>
#include <cuda_fp16.h>
#include <cstdint>

#define NQ 8
#define BINS 1024
#define DIM 256
#define BB 8
#define TT 8192
#define NTOK (BB*TT)            // 65536
#define MT 128
#define NBLK (NTOK/MT)          // 512
#define QOFF 16777216
#define COFF (QOFF + NQ*NTOK)
#define INV2048 4.8828125e-4f

#define ASTR_H 264              // A row stride in halfs (528 B)
#define ASTR_B 528
#define A_BYTES (128*ASTR_B)    // 67584
#define CHUNK_B 16384           // one B chunk: hi only, 32 rows x 512B swizzled

#define SO_CBSQ 0
#define SO_SIDX 4096
#define SO_SSQ  4608
#define SO_MBAR 4672
#define SO_RSQ  4736
#define SO_FCNT 5248
#define SO_FTOK 5264
#define SO_FESC 5776
#define SO_CAND 6288            // 128 x 12 ints
#define SO_AHI  12544
#define SO_ALO  (SO_AHI + A_BYTES)     // 80128
#define SO_B    (SO_ALO + A_BYTES)     // 147712
#define SMEM_BYTES (SO_B + 2*CHUNK_B)  // 180480

__device__ __align__(128) unsigned char g_bimg[(size_t)NQ*32*CHUNK_B]; // 4MB hi image
__device__ float g_cbsq[NQ*BINS];
__device__ int   g_cmaxbits[NQ];       // max ||c||^2 bits per q (atomicMax, idempotent)
__device__ float g_ssq[NQ*NBLK];

static __device__ __forceinline__ uint32_t smem_u32(const void* p){
    uint32_t a;
    asm("{ .reg .u64 t; cvta.to.shared.u64 t, %1; cvt.u32.u64 %0, t; }":"=r"(a):"l"(p));
    return a;
}
static __device__ __forceinline__ void split2(float v, __half& hi, __half& lo){
    hi = __float2half_rn(v);
    lo = __float2half_rn((v - __half2float(hi)) * 2048.0f);
}
#define MBAR_INIT(a,c) asm volatile("mbarrier.init.shared.b64 [%0], %1;"::"r"(a),"r"(c):"memory")
#define MBAR_EXPECT_TX(a,b) asm volatile("mbarrier.arrive.expect_tx.shared.b64 _, [%0], %1;"::"r"(a),"r"(b):"memory")
static __device__ __forceinline__ void mbar_wait(uint32_t a, uint32_t ph){
    asm volatile("{\n\t.reg .pred P;\nW%=: mbarrier.try_wait.parity.acquire.cta.shared::cta.b64 P, [%0], %1, 0x989680;\n\t@!P bra W%=;\n\t}"
        ::"r"(a),"r"(ph):"memory");
}
static __device__ __forceinline__ void bulkcp(uint32_t dst, const void* src,
                                              uint32_t bytes, uint32_t mb){
    asm volatile("cp.async.bulk.shared::cta.global.mbarrier::complete_tx::bytes [%0], [%1], %2, [%3];"
        ::"r"(dst),"l"(src),"r"(bytes),"r"(mb):"memory");
}
static __device__ __forceinline__ void ldsm4(uint32_t* r, uint32_t a){
    asm volatile("ldmatrix.sync.aligned.m8n8.x4.shared.b16 {%0,%1,%2,%3}, [%4];"
        :"=r"(r[0]),"=r"(r[1]),"=r"(r[2]),"=r"(r[3]):"r"(a));
}
static __device__ __forceinline__ void mma16816(float* c, const uint32_t* a,
                                                uint32_t b0, uint32_t b1){
    asm volatile("mma.sync.aligned.m16n8k16.row.col.f32.f16.f16.f32 "
        "{%0,%1,%2,%3}, {%4,%5,%6,%7}, {%8,%9}, {%0,%1,%2,%3};"
        : "+f"(c[0]),"+f"(c[1]),"+f"(c[2]),"+f"(c[3])
        : "r"(a[0]),"r"(a[1]),"r"(a[2]),"r"(a[3]),"r"(b0),"r"(b1));
}
// sorted top-4 insert (ascending; ties keep earlier/lower index)
#define INS4(vv, xx, nv, ni) do{ \
  if ((nv) < vv[3]) { \
    if ((nv) < vv[1]) { \
      vv[3]=vv[2]; xx[3]=xx[2]; vv[2]=vv[1]; xx[2]=xx[1]; \
      if ((nv) < vv[0]) { vv[1]=vv[0]; xx[1]=xx[0]; vv[0]=(nv); xx[0]=(ni); } \
      else { vv[1]=(nv); xx[1]=(ni); } \
    } else { \
      if ((nv) < vv[2]) { vv[3]=vv[2]; xx[3]=xx[2]; vv[2]=(nv); xx[2]=(ni); } \
      else { vv[3]=(nv); xx[3]=(ni); } \
    } \
  } }while(0)

// ---- prep: fp16-hi codebook image, pre-swizzled per 32-bin chunk ------------
__global__ void rvq_prep_kernel(const float* __restrict__ cbs){
    int id = blockIdx.x*blockDim.x + threadIdx.x;
    if (id >= NQ*BINS*DIM) return;
    int d = id & 255, j = (id>>8) & 1023, q = id>>18;
    __half hi = __float2half_rn(cbs[id]);
    int jc = j>>5, jr = j&31;
    uint32_t unit = (uint32_t)(d>>3);
    uint32_t off = (uint32_t)jr*512u + ((unit ^ (uint32_t)(jr&7))<<4) + (uint32_t)(d&7)*2u;
    *(__half*)(g_bimg + (size_t)(q*32+jc)*CHUNK_B + off) = hi;
}

__global__ void rvq_cbsq_kernel(const float* __restrict__ cbs){
    int id = blockIdx.x*blockDim.x + threadIdx.x;
    if (id >= NQ*BINS) return;
    const float* c = cbs + (size_t)id*DIM;
    float s0=0,s1=0,s2=0,s3=0;
    #pragma unroll 8
    for (int d=0; d<DIM; d+=4){
        float4 v = *(const float4*)(c+d);
        s0=fmaf(v.x,v.x,s0); s1=fmaf(v.y,v.y,s1); s2=fmaf(v.z,v.z,s2); s3=fmaf(v.w,v.w,s3);
    }
    float n2 = (s0+s1)+(s2+s3);
    g_cbsq[id] = n2;
    atomicMax(&g_cmaxbits[id>>10], __float_as_int(n2));
}

// ---- main -------------------------------------------------------------------
__global__ __launch_bounds__(256,1)
void rvq_main_kernel(const float* __restrict__ x, const float* __restrict__ cbs,
                     float* __restrict__ out){
    extern __shared__ char smc[];
    const uint32_t sb = smem_u32(smc);
    const int tid = threadIdx.x, l = tid&31, w = tid>>5, bid = blockIdx.x;
    const int b = bid>>6, t0 = (bid&63)<<7;
    const float* xblk = x + ((size_t)b*DIM)*TT + t0;
    float* cbsq_s = (float*)(smc+SO_CBSQ);
    int*   sidx   = (int*)(smc+SO_SIDX);
    float* ssqs   = (float*)(smc+SO_SSQ);
    float* rsq    = (float*)(smc+SO_RSQ);
    int*   fcnt   = (int*)(smc+SO_FCNT);
    int*   ftok   = (int*)(smc+SO_FTOK);
    int*   fesc   = (int*)(smc+SO_FESC);
    int*   cand   = (int*)(smc+SO_CAND);   // [128][12]
    __half* pH = (__half*)(smc+SO_AHI);
    __half* pL = (__half*)(smc+SO_ALO);

    if (tid==0){ MBAR_INIT(sb+SO_MBAR,1); MBAR_INIT(sb+SO_MBAR+8,1); }

    // residual = x, split fp16 hi/lo ([m][d])
    for (int i=tid; i<DIM*MT; i+=256){
        int d = i>>7, m = i&127;
        __half hi, lo; split2(xblk[(size_t)d*TT+m], hi, lo);
        int o = m*ASTR_H + d;
        pH[o] = hi; pL[o] = lo;
    }
    __syncthreads();
    if (tid < MT){   // exact ||r0||^2 per token (bound seed)
        float s = 0.f;
        for (int d=0; d<DIM; ++d){
            int o = tid*ASTR_H + d;
            float v = __half2float(pH[o]) + __half2float(pL[o])*INV2048;
            s = fmaf(v, v, s);
        }
        rsq[tid] = s;
    }
    __syncthreads();

    const uint32_t aW = sb + SO_AHI + (w*16 + (l&15))*ASTR_B + (l>>4)*16;
    const int nr  = (l&7) | ((l&16)>>1);
    const int suu = (l>>3)&1;
    const uint32_t xorv = (uint32_t)(nr&7);
    const uint32_t bRow = sb + SO_B + (uint32_t)nr*512u;
    const int grpLead = l & ~3;

    int ph[2] = {0,0};

    for (int q=0; q<NQ; ++q){
        const float* cbq = cbs + (size_t)q*BINS*DIM;
        for (int i=tid; i<BINS; i+=256) cbsq_s[i] = g_cbsq[q*BINS+i];
        if (tid==0) fcnt[0] = 0;
        const float CE = 1.96e-3f * sqrtf(__int_as_float(g_cmaxbits[q]));
        __syncthreads();

        if (tid==0){
            MBAR_EXPECT_TX(sb+SO_MBAR, CHUNK_B);
            bulkcp(sb+SO_B, g_bimg + (size_t)(q*32)*CHUNK_B, CHUNK_B, sb+SO_MBAR);
        }

        float v0[4] = {3.4e38f,3.4e38f,3.4e38f,3.4e38f};
        float v1[4] = {3.4e38f,3.4e38f,3.4e38f,3.4e38f};
        int   i0[4] = {0,0,0,0}, i1[4] = {0,0,0,0};

        for (int c=0; c<32; ++c){
            const int s = c&1;
            if (c < 31 && tid==0){
                const int s2 = (c+1)&1;
                MBAR_EXPECT_TX(sb+SO_MBAR+8*s2, CHUNK_B);
                bulkcp(sb+SO_B+(uint32_t)s2*CHUNK_B,
                       g_bimg + (size_t)(q*32+c+1)*CHUNK_B, CHUNK_B, sb+SO_MBAR+8*s2);
            }
            mbar_wait(sb+SO_MBAR+8*s, ph[s]); ph[s]^=1;

            float acc[4][4];
            #pragma unroll
            for (int t=0;t<4;++t)
                #pragma unroll
                for (int i=0;i<4;++i) acc[t][i]=0.f;

            const uint32_t bbase = bRow + (uint32_t)s*CHUNK_B;
            #pragma unroll 4
            for (int kt=0; kt<16; ++kt){
                uint32_t ah[4];
                ldsm4(ah, aW + kt*32);
                const uint32_t cbyte = ((((uint32_t)(kt*2+suu)) ^ xorv) << 4);
                #pragma unroll
                for (int g=0; g<2; ++g){
                    uint32_t bh[4];
                    ldsm4(bh, bbase + (uint32_t)g*8192u + cbyte);
                    mma16816(acc[g*2],   ah, bh[0], bh[1]);
                    mma16816(acc[g*2+1], ah, bh[2], bh[3]);
                }
            }

            #pragma unroll
            for (int t=0;t<4;++t){
                int n = c*32 + t*8 + (l&3)*2;
                float d0 = cbsq_s[n]   - 2.f*acc[t][0];
                float d1 = cbsq_s[n+1] - 2.f*acc[t][1];
                float d2 = cbsq_s[n]   - 2.f*acc[t][2];
                float d3 = cbsq_s[n+1] - 2.f*acc[t][3];
                INS4(v0,i0,d0,n); INS4(v0,i0,d1,n+1);
                INS4(v1,i1,d2,n); INS4(v1,i1,d3,n+1);
            }
            __syncthreads();
        }

        // per-slot: merge 4 lanes -> global best1/best2; accept or flag
        #pragma unroll
        for (int slot=0; slot<2; ++slot){
            float* vv = slot ? v1 : v0;
            int*   xx = slot ? i1 : i0;
            float b1v = vv[0], b2v = vv[1];
            int   b1i = xx[0];
            #pragma unroll
            for (int off=1; off<=2; off<<=1){
                float o1v = __shfl_xor_sync(0xFFFFFFFFu, b1v, off);
                int   o1i = __shfl_xor_sync(0xFFFFFFFFu, b1i, off);
                float o2v = __shfl_xor_sync(0xFFFFFFFFu, b2v, off);
                if (o1v < b1v || (o1v == b1v && o1i < b1i)){
                    b2v = fminf(b1v, o2v); b1v = o1v; b1i = o1i;
                } else b2v = fminf(b2v, o1v);
            }
            int m = w*16 + (l>>2) + slot*8;
            float E = CE * sqrtf(fmaxf(rsq[m], 0.f));
            float epsw = 2.1f*E + 0.02f;
            float W = b1v + epsw;
            bool flag = (b2v <= W);
            int fi = -1;
            if (flag && (l&3)==0) fi = atomicAdd(fcnt, 1);
            fi = __shfl_sync(0xFFFFFFFFu, fi, grpLead);
            int escb = (vv[3] <= W) ? 1 : 0;
            escb |= __shfl_xor_sync(0xFFFFFFFFu, escb, 1);
            escb |= __shfl_xor_sync(0xFFFFFFFFu, escb, 2);
            if (flag){
                if ((l&3)==0){ ftok[fi] = m; fesc[fi] = escb; }
                #pragma unroll
                for (int k=0;k<3;++k)
                    cand[fi*12 + (l&3)*3 + k] = (vv[k] <= W) ? xx[k] : -1;
            } else if ((l&3)==0){
                sidx[m] = b1i;
                out[QOFF + ((size_t)(q*BB+b))*TT + t0 + m] = (float)b1i;
                rsq[m] = fmaxf(rsq[m] + b1v + epsw, 0.f);
            }
        }
        __syncthreads();

        // recheck flagged tokens: exact fp32 over candidates (or full scan)
        {
            const int nf = fcnt[0];
            for (int f = w; f < nf; f += 8){
                int m = ftok[f], esc = fesc[f];
                float rv[8];
                int o = m*ASTR_H + l*8;
                #pragma unroll
                for (int e=0; e<8; ++e)
                    rv[e] = __half2float(pH[o+e]) + __half2float(pL[o+e])*INV2048;
                float be = 3.4e38f; int bj = 0;
                if (!esc){
                    for (int k=0; k<12; ++k){
                        int j = cand[f*12+k];
                        if (j < 0) continue;
                        const float4* cr = (const float4*)(cbq + (size_t)j*DIM + l*8);
                        float4 ca = cr[0], cb2 = cr[1];
                        float s = rv[0]*ca.x + rv[1]*ca.y + rv[2]*ca.z + rv[3]*ca.w
                                + rv[4]*cb2.x + rv[5]*cb2.y + rv[6]*cb2.z + rv[7]*cb2.w;
                        #pragma unroll
                        for (int off2=16; off2>0; off2>>=1) s += __shfl_xor_sync(0xFFFFFFFFu, s, off2);
                        float e2 = cbsq_s[j] - 2.f*s;
                        if (e2 < be || (e2 == be && j < bj)){ be = e2; bj = j; }
                    }
                } else {
                    for (int j=0; j<BINS; ++j){
                        const float4* cr = (const float4*)(cbq + (size_t)j*DIM + l*8);
                        float4 ca = cr[0], cb2 = cr[1];
                        float s = rv[0]*ca.x + rv[1]*ca.y + rv[2]*ca.z + rv[3]*ca.w
                                + rv[4]*cb2.x + rv[5]*cb2.y + rv[6]*cb2.z + rv[7]*cb2.w;
                        #pragma unroll
                        for (int off2=16; off2>0; off2>>=1) s += __shfl_xor_sync(0xFFFFFFFFu, s, off2);
                        float e2 = cbsq_s[j] - 2.f*s;
                        if (e2 < be){ be = e2; bj = j; }
                    }
                }
                if (l==0){
                    sidx[m] = bj;
                    out[QOFF + ((size_t)(q*BB+b))*TT + t0 + m] = (float)bj;
                    rsq[m] = fmaxf(rsq[m] + be + 0.05f, 0.f);
                }
            }
        }
        __syncthreads();

        // residual update (tid = dim d): reconstruct-subtract-resplit + exact ssq
        {
            float ssq = 0.f;
            #pragma unroll 4
            for (int m=0; m<MT; ++m){
                int ix = sidx[m];
                float cv = __ldg(cbq + (size_t)ix*DIM + tid);
                int o = m*ASTR_H + tid;
                float r = __half2float(pH[o]) + __half2float(pL[o])*INV2048;
                float rn = r - cv;
                __half hi, lo; split2(rn, hi, lo);
                pH[o]=hi; pL[o]=lo;
                ssq = fmaf(rn, rn, ssq);
            }
            #pragma unroll
            for (int o2=16;o2>0;o2>>=1) ssq += __shfl_xor_sync(0xFFFFFFFFu, ssq, o2);
            if (l==0) ssqs[w] = ssq;
            __syncthreads();
            if (tid==0){
                float sacc=0.f;
                #pragma unroll
                for (int ww=0; ww<8; ++ww) sacc += ssqs[ww];
                g_ssq[q*NBLK+bid] = sacc;
            }
            __syncthreads();
        }
    }

    // quantized = x - r_final
    for (int i=tid; i<DIM*MT; i+=256){
        int d = i>>7, m = i&127;
        int o = m*ASTR_H + d;
        float r = __half2float(pH[o]) + __half2float(pL[o])*INV2048;
        out[((size_t)b*DIM+d)*TT + t0 + m] = xblk[(size_t)d*TT+m] - r;
    }
}

// ---- finalize ---------------------------------------------------------------
__global__ void rvq_finalize_kernel(const int* __restrict__ sr_raw, float* __restrict__ out){
    __shared__ float red[8];
    const int tid = threadIdx.x;
    float s = 0.f;
    #pragma unroll
    for (int i=0; i<NQ*NBLK/256; ++i) s += g_ssq[tid + i*256];
    #pragma unroll
    for (int o=16;o>0;o>>=1) s += __shfl_xor_sync(0xFFFFFFFFu, s, o);
    if ((tid&31)==0) red[tid>>5] = s;
    __syncthreads();
    if (tid==0){
        float tot=0.f;
        #pragma unroll
        for (int w=0; w<8; ++w) tot += red[w];
        int iv = sr_raw[0];
        float sr = (iv > 0 && iv < 100000000) ? (float)iv : __int_as_float(iv);
        out[COFF+0] = (float)NQ * 10.0f * (sr / 1000.0f);
        out[COFF+1] = tot * (0.25f / ((float)((size_t)NTOK*DIM))) / (float)NQ;
    }
}

extern "C" void kernel_launch(void* const* d_in, const int* in_sizes, int n_in,
                              void* d_out, int out_size){
    const float* x   = (const float*)d_in[0];
    const int*   sr  = (const int*)d_in[1];
    const float* cbs = (const float*)d_in[2];
    float* out = (float*)d_out;
    cudaFuncSetAttribute(rvq_main_kernel, cudaFuncAttributeMaxDynamicSharedMemorySize, SMEM_BYTES);
    rvq_prep_kernel<<<(NQ*BINS*DIM+255)/256, 256>>>(cbs);
    rvq_cbsq_kernel<<<(NQ*BINS+255)/256, 256>>>(cbs);
    rvq_main_kernel<<<NBLK, 256, SMEM_BYTES>>>(x, cbs, out);
    rvq_finalize_kernel<<<1, 256>>>(sr, out);
}

// round 11
// speedup vs baseline: 2.7177x; 1.0620x over previous
#include <cuda_runtime.h>
#include <cuda_fp16.h>
#include <cstdint>

#define NQ 8
#define BINS 1024
#define DIM 256
#define BB 8
#define TT 8192
#define NTOK (BB*TT)            // 65536
#define MT 128
#define NBLK (NTOK/MT)          // 512
#define QOFF 16777216
#define COFF (QOFF + NQ*NTOK)
#define INV2048 4.8828125e-4f

#define ASTR_H 264              // A row stride in halfs (528 B)
#define ASTR_B 528
#define A_BYTES (128*ASTR_B)    // 67584
#define CHUNK_B 16384           // one B chunk: hi only, 32 rows x 512B swizzled
#define NCHUNKS 256             // NQ*32 global chunk sequence

#define SO_CBSQ 0
#define SO_SIDX 4096
#define SO_SSQ  4608
#define SO_MBAR 4672            // full[4] @ +0..31, empty[4] @ +32..63
#define SO_RSQ  4736
#define SO_FCNT 5248
#define SO_FTOK 5264
#define SO_FESC 5776
#define SO_CAND 6288            // 128 x 12 ints
#define SO_AHI  12544
#define SO_ALO  (SO_AHI + A_BYTES)     // 80128
#define SO_B    (SO_ALO + A_BYTES)     // 147712
#define SMEM_BYTES (SO_B + 4*CHUNK_B)  // 213248

__device__ __align__(128) unsigned char g_bimg[(size_t)NCHUNKS*CHUNK_B]; // 4MB hi image
__device__ float g_cbsq[NQ*BINS];
__device__ int   g_cmaxbits[NQ];
__device__ float g_ssq[NQ*NBLK];

static __device__ __forceinline__ uint32_t smem_u32(const void* p){
    uint32_t a;
    asm("{ .reg .u64 t; cvta.to.shared.u64 t, %1; cvt.u32.u64 %0, t; }":"=r"(a):"l"(p));
    return a;
}
static __device__ __forceinline__ void split2(float v, __half& hi, __half& lo){
    hi = __float2half_rn(v);
    lo = __float2half_rn((v - __half2float(hi)) * 2048.0f);
}
#define MBAR_INIT(a,c) asm volatile("mbarrier.init.shared.b64 [%0], %1;"::"r"(a),"r"(c):"memory")
#define MBAR_ARRIVE(a) asm volatile("mbarrier.arrive.shared.b64 _, [%0];"::"r"(a):"memory")
#define MBAR_EXPECT_TX(a,b) asm volatile("mbarrier.arrive.expect_tx.shared.b64 _, [%0], %1;"::"r"(a),"r"(b):"memory")
static __device__ __forceinline__ void mbar_wait(uint32_t a, uint32_t ph){
    asm volatile("{\n\t.reg .pred P;\nW%=: mbarrier.try_wait.parity.acquire.cta.shared::cta.b64 P, [%0], %1, 0x989680;\n\t@!P bra W%=;\n\t}"
        ::"r"(a),"r"(ph):"memory");
}
static __device__ __forceinline__ void bulkcp(uint32_t dst, const void* src,
                                              uint32_t bytes, uint32_t mb){
    asm volatile("cp.async.bulk.shared::cta.global.mbarrier::complete_tx::bytes [%0], [%1], %2, [%3];"
        ::"r"(dst),"l"(src),"r"(bytes),"r"(mb):"memory");
}
static __device__ __forceinline__ void ldsm4(uint32_t* r, uint32_t a){
    asm volatile("ldmatrix.sync.aligned.m8n8.x4.shared.b16 {%0,%1,%2,%3}, [%4];"
        :"=r"(r[0]),"=r"(r[1]),"=r"(r[2]),"=r"(r[3]):"r"(a));
}
static __device__ __forceinline__ void mma16816(float* c, const uint32_t* a,
                                                uint32_t b0, uint32_t b1){
    asm volatile("mma.sync.aligned.m16n8k16.row.col.f32.f16.f16.f32 "
        "{%0,%1,%2,%3}, {%4,%5,%6,%7}, {%8,%9}, {%0,%1,%2,%3};"
        : "+f"(c[0]),"+f"(c[1]),"+f"(c[2]),"+f"(c[3])
        : "r"(a[0]),"r"(a[1]),"r"(a[2]),"r"(a[3]),"r"(b0),"r"(b1));
}
#define INS4(vv, xx, nv, ni) do{ \
  if ((nv) < vv[3]) { \
    if ((nv) < vv[1]) { \
      vv[3]=vv[2]; xx[3]=xx[2]; vv[2]=vv[1]; xx[2]=xx[1]; \
      if ((nv) < vv[0]) { vv[1]=vv[0]; xx[1]=xx[0]; vv[0]=(nv); xx[0]=(ni); } \
      else { vv[1]=(nv); xx[1]=(ni); } \
    } else { \
      if ((nv) < vv[2]) { vv[3]=vv[2]; xx[3]=xx[2]; vv[2]=(nv); xx[2]=(ni); } \
      else { vv[3]=(nv); xx[3]=(ni); } \
    } \
  } }while(0)

__global__ void rvq_prep_kernel(const float* __restrict__ cbs){
    int id = blockIdx.x*blockDim.x + threadIdx.x;
    if (id >= NQ*BINS*DIM) return;
    int d = id & 255, j = (id>>8) & 1023, q = id>>18;
    __half hi = __float2half_rn(cbs[id]);
    int jc = j>>5, jr = j&31;
    uint32_t unit = (uint32_t)(d>>3);
    uint32_t off = (uint32_t)jr*512u + ((unit ^ (uint32_t)(jr&7))<<4) + (uint32_t)(d&7)*2u;
    *(__half*)(g_bimg + (size_t)(q*32+jc)*CHUNK_B + off) = hi;
}

__global__ void rvq_cbsq_kernel(const float* __restrict__ cbs){
    int id = blockIdx.x*blockDim.x + threadIdx.x;
    if (id >= NQ*BINS) return;
    const float* c = cbs + (size_t)id*DIM;
    float s0=0,s1=0,s2=0,s3=0;
    #pragma unroll 8
    for (int d=0; d<DIM; d+=4){
        float4 v = *(const float4*)(c+d);
        s0=fmaf(v.x,v.x,s0); s1=fmaf(v.y,v.y,s1); s2=fmaf(v.z,v.z,s2); s3=fmaf(v.w,v.w,s3);
    }
    float n2 = (s0+s1)+(s2+s3);
    g_cbsq[id] = n2;
    atomicMax(&g_cmaxbits[id>>10], __float_as_int(n2));
}

__global__ __launch_bounds__(256,1)
void rvq_main_kernel(const float* __restrict__ x, const float* __restrict__ cbs,
                     float* __restrict__ out){
    extern __shared__ char smc[];
    const uint32_t sb = smem_u32(smc);
    const int tid = threadIdx.x, l = tid&31, w = tid>>5, bid = blockIdx.x;
    const int b = bid>>6, t0 = (bid&63)<<7;
    const float* xblk = x + ((size_t)b*DIM)*TT + t0;
    float* cbsq_s = (float*)(smc+SO_CBSQ);
    int*   sidx   = (int*)(smc+SO_SIDX);
    float* ssqs   = (float*)(smc+SO_SSQ);
    float* rsq    = (float*)(smc+SO_RSQ);
    int*   fcnt   = (int*)(smc+SO_FCNT);
    int*   ftok   = (int*)(smc+SO_FTOK);
    int*   fesc   = (int*)(smc+SO_FESC);
    int*   cand   = (int*)(smc+SO_CAND);
    __half* pH = (__half*)(smc+SO_AHI);
    __half* pL = (__half*)(smc+SO_ALO);
    #define FULLB(i)  (sb+SO_MBAR + (uint32_t)(i)*8u)
    #define EMPTYB(i) (sb+SO_MBAR + 32u + (uint32_t)(i)*8u)

    if (tid==0){
        #pragma unroll
        for (int i=0;i<4;++i){ MBAR_INIT(FULLB(i),1); MBAR_INIT(EMPTYB(i),8); }
    }

    for (int i=tid; i<DIM*MT; i+=256){
        int d = i>>7, m = i&127;
        __half hi, lo; split2(xblk[(size_t)d*TT+m], hi, lo);
        int o = m*ASTR_H + d;
        pH[o] = hi; pL[o] = lo;
    }
    __syncthreads();
    if (tid < MT){
        float s = 0.f;
        for (int d=0; d<DIM; ++d){
            int o = tid*ASTR_H + d;
            float v = __half2float(pH[o]) + __half2float(pL[o])*INV2048;
            s = fmaf(v, v, s);
        }
        rsq[tid] = s;
    }
    __syncthreads();

    const uint32_t aW = sb + SO_AHI + (w*16 + (l&15))*ASTR_B + (l>>4)*16;
    const int nr  = (l&7) | ((l&16)>>1);
    const int suu = (l>>3)&1;
    const uint32_t xorv = (uint32_t)(nr&7);
    const uint32_t bRow = sb + SO_B + (uint32_t)nr*512u;
    const int grpLead = l & ~3;

    int pf[4] = {0,0,0,0};   // consumer full phases
    int pe[4] = {1,1,1,1};   // producer empty phases (fresh-barrier pass)

    // prologue: prefetch global chunks 0,1,2
    if (tid==0){
        #pragma unroll
        for (int p=0; p<3; ++p){
            mbar_wait(EMPTYB(p), pe[p]); pe[p]^=1;
            MBAR_EXPECT_TX(FULLB(p), CHUNK_B);
            bulkcp(sb+SO_B+(uint32_t)p*CHUNK_B, g_bimg + (size_t)p*CHUNK_B, CHUNK_B, FULLB(p));
        }
    }

    for (int q=0; q<NQ; ++q){
        const float* cbq = cbs + (size_t)q*BINS*DIM;
        for (int i=tid; i<BINS; i+=256) cbsq_s[i] = g_cbsq[q*BINS+i];
        if (tid==0) fcnt[0] = 0;
        const float CE = 1.96e-3f * sqrtf(__int_as_float(g_cmaxbits[q]));
        __syncthreads();

        float v0[4] = {3.4e38f,3.4e38f,3.4e38f,3.4e38f};
        float v1[4] = {3.4e38f,3.4e38f,3.4e38f,3.4e38f};
        int   i0[4] = {0,0,0,0}, i1[4] = {0,0,0,0};

        for (int c=0; c<32; ++c){
            const int G = q*32 + c;
            if (tid==0 && G+3 < NCHUNKS){
                const int s3 = (G+3)&3;
                mbar_wait(EMPTYB(s3), pe[s3]); pe[s3]^=1;
                MBAR_EXPECT_TX(FULLB(s3), CHUNK_B);
                bulkcp(sb+SO_B+(uint32_t)s3*CHUNK_B,
                       g_bimg + (size_t)(G+3)*CHUNK_B, CHUNK_B, FULLB(s3));
            }
            const int s = G&3;
            mbar_wait(FULLB(s), pf[s]); pf[s]^=1;

            float acc[4][4];
            #pragma unroll
            for (int t=0;t<4;++t)
                #pragma unroll
                for (int i=0;i<4;++i) acc[t][i]=0.f;

            const uint32_t bbase = bRow + (uint32_t)s*CHUNK_B;
            #pragma unroll 4
            for (int kt=0; kt<16; ++kt){
                uint32_t ah[4];
                ldsm4(ah, aW + kt*32);
                const uint32_t cbyte = ((((uint32_t)(kt*2+suu)) ^ xorv) << 4);
                #pragma unroll
                for (int g=0; g<2; ++g){
                    uint32_t bh[4];
                    ldsm4(bh, bbase + (uint32_t)g*8192u + cbyte);
                    mma16816(acc[g*2],   ah, bh[0], bh[1]);
                    mma16816(acc[g*2+1], ah, bh[2], bh[3]);
                }
            }
            if (l==0) MBAR_ARRIVE(EMPTYB(s));   // B regs captured; buffer reusable

            #pragma unroll
            for (int t=0;t<4;++t){
                int n = c*32 + t*8 + (l&3)*2;
                float d0 = cbsq_s[n]   - 2.f*acc[t][0];
                float d1 = cbsq_s[n+1] - 2.f*acc[t][1];
                float d2 = cbsq_s[n]   - 2.f*acc[t][2];
                float d3 = cbsq_s[n+1] - 2.f*acc[t][3];
                INS4(v0,i0,d0,n); INS4(v0,i0,d1,n+1);
                INS4(v1,i1,d2,n); INS4(v1,i1,d3,n+1);
            }
        }

        #pragma unroll
        for (int slot=0; slot<2; ++slot){
            float* vv = slot ? v1 : v0;
            int*   xx = slot ? i1 : i0;
            float b1v = vv[0], b2v = vv[1];
            int   b1i = xx[0];
            #pragma unroll
            for (int off=1; off<=2; off<<=1){
                float o1v = __shfl_xor_sync(0xFFFFFFFFu, b1v, off);
                int   o1i = __shfl_xor_sync(0xFFFFFFFFu, b1i, off);
                float o2v = __shfl_xor_sync(0xFFFFFFFFu, b2v, off);
                if (o1v < b1v || (o1v == b1v && o1i < b1i)){
                    b2v = fminf(b1v, o2v); b1v = o1v; b1i = o1i;
                } else b2v = fminf(b2v, o1v);
            }
            int m = w*16 + (l>>2) + slot*8;
            float E = CE * sqrtf(fmaxf(rsq[m], 0.f));
            float epsw = 2.1f*E + 0.02f;
            float W = b1v + epsw;
            bool flag = (b2v <= W);
            int fi = -1;
            if (flag && (l&3)==0) fi = atomicAdd(fcnt, 1);
            fi = __shfl_sync(0xFFFFFFFFu, fi, grpLead);
            int escb = (vv[3] <= W) ? 1 : 0;
            escb |= __shfl_xor_sync(0xFFFFFFFFu, escb, 1);
            escb |= __shfl_xor_sync(0xFFFFFFFFu, escb, 2);
            if (flag){
                if ((l&3)==0){ ftok[fi] = m; fesc[fi] = escb; }
                #pragma unroll
                for (int k=0;k<3;++k)
                    cand[fi*12 + (l&3)*3 + k] = (vv[k] <= W) ? xx[k] : -1;
            } else if ((l&3)==0){
                sidx[m] = b1i;
                out[QOFF + ((size_t)(q*BB+b))*TT + t0 + m] = (float)b1i;
                rsq[m] = fmaxf(rsq[m] + b1v + epsw, 0.f);
            }
        }
        __syncthreads();

        {
            const int nf = fcnt[0];
            for (int f = w; f < nf; f += 8){
                int m = ftok[f], esc = fesc[f];
                float rv[8];
                int o = m*ASTR_H + l*8;
                #pragma unroll
                for (int e=0; e<8; ++e)
                    rv[e] = __half2float(pH[o+e]) + __half2float(pL[o+e])*INV2048;
                float be = 3.4e38f; int bj = 0;
                if (!esc){
                    for (int k=0; k<12; ++k){
                        int j = cand[f*12+k];
                        if (j < 0) continue;
                        const float4* cr = (const float4*)(cbq + (size_t)j*DIM + l*8);
                        float4 ca = cr[0], cb2 = cr[1];
                        float s = rv[0]*ca.x + rv[1]*ca.y + rv[2]*ca.z + rv[3]*ca.w
                                + rv[4]*cb2.x + rv[5]*cb2.y + rv[6]*cb2.z + rv[7]*cb2.w;
                        #pragma unroll
                        for (int off2=16; off2>0; off2>>=1) s += __shfl_xor_sync(0xFFFFFFFFu, s, off2);
                        float e2 = cbsq_s[j] - 2.f*s;
                        if (e2 < be || (e2 == be && j < bj)){ be = e2; bj = j; }
                    }
                } else {
                    for (int j=0; j<BINS; ++j){
                        const float4* cr = (const float4*)(cbq + (size_t)j*DIM + l*8);
                        float4 ca = cr[0], cb2 = cr[1];
                        float s = rv[0]*ca.x + rv[1]*ca.y + rv[2]*ca.z + rv[3]*ca.w
                                + rv[4]*cb2.x + rv[5]*cb2.y + rv[6]*cb2.z + rv[7]*cb2.w;
                        #pragma unroll
                        for (int off2=16; off2>0; off2>>=1) s += __shfl_xor_sync(0xFFFFFFFFu, s, off2);
                        float e2 = cbsq_s[j] - 2.f*s;
                        if (e2 < be){ be = e2; bj = j; }
                    }
                }
                if (l==0){
                    sidx[m] = bj;
                    out[QOFF + ((size_t)(q*BB+b))*TT + t0 + m] = (float)bj;
                    rsq[m] = fmaxf(rsq[m] + be + 0.05f, 0.f);
                }
            }
        }
        __syncthreads();

        {
            float ssq = 0.f;
            #pragma unroll 4
            for (int m=0; m<MT; ++m){
                int ix = sidx[m];
                float cv = __ldg(cbq + (size_t)ix*DIM + tid);
                int o = m*ASTR_H + tid;
                float r = __half2float(pH[o]) + __half2float(pL[o])*INV2048;
                float rn = r - cv;
                __half hi, lo; split2(rn, hi, lo);
                pH[o]=hi; pL[o]=lo;
                ssq = fmaf(rn, rn, ssq);
            }
            #pragma unroll
            for (int o2=16;o2>0;o2>>=1) ssq += __shfl_xor_sync(0xFFFFFFFFu, ssq, o2);
            if (l==0) ssqs[w] = ssq;
            __syncthreads();
            if (tid==0){
                float sacc=0.f;
                #pragma unroll
                for (int ww=0; ww<8; ++ww) sacc += ssqs[ww];
                g_ssq[q*NBLK+bid] = sacc;
            }
            __syncthreads();
        }
    }

    for (int i=tid; i<DIM*MT; i+=256){
        int d = i>>7, m = i&127;
        int o = m*ASTR_H + d;
        float r = __half2float(pH[o]) + __half2float(pL[o])*INV2048;
        out[((size_t)b*DIM+d)*TT + t0 + m] = xblk[(size_t)d*TT+m] - r;
    }
}

__global__ void rvq_finalize_kernel(const int* __restrict__ sr_raw, float* __restrict__ out){
    __shared__ float red[8];
    const int tid = threadIdx.x;
    float s = 0.f;
    #pragma unroll
    for (int i=0; i<NQ*NBLK/256; ++i) s += g_ssq[tid + i*256];
    #pragma unroll
    for (int o=16;o>0;o>>=1) s += __shfl_xor_sync(0xFFFFFFFFu, s, o);
    if ((tid&31)==0) red[tid>>5] = s;
    __syncthreads();
    if (tid==0){
        float tot=0.f;
        #pragma unroll
        for (int w=0; w<8; ++w) tot += red[w];
        int iv = sr_raw[0];
        float sr = (iv > 0 && iv < 100000000) ? (float)iv : __int_as_float(iv);
        out[COFF+0] = (float)NQ * 10.0f * (sr / 1000.0f);
        out[COFF+1] = tot * (0.25f / ((float)((size_t)NTOK*DIM))) / (float)NQ;
    }
}

extern "C" void kernel_launch(void* const* d_in, const int* in_sizes, int n_in,
                              void* d_out, int out_size){
    const float* x   = (const float*)d_in[0];
    const int*   sr  = (const int*)d_in[1];
    const float* cbs = (const float*)d_in[2];
    float* out = (float*)d_out;
    cudaFuncSetAttribute(rvq_main_kernel, cudaFuncAttributeMaxDynamicSharedMemorySize, SMEM_BYTES);
    rvq_prep_kernel<<<(NQ*BINS*DIM+255)/256, 256>>>(cbs);
    rvq_cbsq_kernel<<<(NQ*BINS+255)/256, 256>>>(cbs);
    rvq_main_kernel<<<NBLK, 256, SMEM_BYTES>>>(x, cbs, out);
    rvq_finalize_kernel<<<1, 256>>>(sr, out);
}

// round 12
// speedup vs baseline: 2.8396x; 1.0448x over previous
#include <cuda_runtime.h>
#include <cuda_fp16.h>
#include <cstdint>

#define NQ 8
#define BINS 1024
#define DIM 256
#define BB 8
#define TT 8192
#define NTOK (BB*TT)            // 65536
#define MT 256
#define NBLK (NTOK/MT)          // 256
#define QOFF 16777216
#define COFF (QOFF + NQ*NTOK)
#define INV2048 4.8828125e-4f

#define ASTR_H 264              // A row stride in halfs (528 B)
#define ASTR_B 528
#define A_BYTES (MT*ASTR_B)     // 135168
#define CHUNK_B 16384
#define NCHUNKS 256

#define SO_CBSQ 0
#define SO_SIDX 4096            // 256 ints
#define SO_SSQ  5120
#define SO_MBAR 5152            // full[4], empty[4]
#define SO_RSQ  5216            // 256 floats
#define SO_FCNT 6240
#define SO_FTOK 6256            // 256 ints
#define SO_FESC 7280            // 256 ints
#define SO_CAND 8304            // 256 x 12 ints
#define SO_AHI  20608
#define SO_B    (SO_AHI + A_BYTES)      // 155776
#define SMEM_BYTES (SO_B + 4*CHUNK_B)   // 221312

__device__ __align__(128) unsigned char g_bimg[(size_t)NCHUNKS*CHUNK_B]; // 4MB
__device__ float g_res[(size_t)NTOK*DIM];   // 67MB exact fp32 residual
__device__ float g_cbsq[NQ*BINS];
__device__ int   g_cmaxbits[NQ];
__device__ float g_ssq[NQ*NBLK];

static __device__ __forceinline__ uint32_t smem_u32(const void* p){
    uint32_t a;
    asm("{ .reg .u64 t; cvta.to.shared.u64 t, %1; cvt.u32.u64 %0, t; }":"=r"(a):"l"(p));
    return a;
}
#define MBAR_INIT(a,c) asm volatile("mbarrier.init.shared.b64 [%0], %1;"::"r"(a),"r"(c):"memory")
#define MBAR_ARRIVE(a) asm volatile("mbarrier.arrive.shared.b64 _, [%0];"::"r"(a):"memory")
#define MBAR_EXPECT_TX(a,b) asm volatile("mbarrier.arrive.expect_tx.shared.b64 _, [%0], %1;"::"r"(a),"r"(b):"memory")
static __device__ __forceinline__ void mbar_wait(uint32_t a, uint32_t ph){
    asm volatile("{\n\t.reg .pred P;\nW%=: mbarrier.try_wait.parity.acquire.cta.shared::cta.b64 P, [%0], %1, 0x989680;\n\t@!P bra W%=;\n\t}"
        ::"r"(a),"r"(ph):"memory");
}
static __device__ __forceinline__ void bulkcp(uint32_t dst, const void* src,
                                              uint32_t bytes, uint32_t mb){
    asm volatile("cp.async.bulk.shared::cta.global.mbarrier::complete_tx::bytes [%0], [%1], %2, [%3];"
        ::"r"(dst),"l"(src),"r"(bytes),"r"(mb):"memory");
}
static __device__ __forceinline__ void ldsm4(uint32_t* r, uint32_t a){
    asm volatile("ldmatrix.sync.aligned.m8n8.x4.shared.b16 {%0,%1,%2,%3}, [%4];"
        :"=r"(r[0]),"=r"(r[1]),"=r"(r[2]),"=r"(r[3]):"r"(a));
}
static __device__ __forceinline__ void mma16816(float* c, const uint32_t* a,
                                                uint32_t b0, uint32_t b1){
    asm volatile("mma.sync.aligned.m16n8k16.row.col.f32.f16.f16.f32 "
        "{%0,%1,%2,%3}, {%4,%5,%6,%7}, {%8,%9}, {%0,%1,%2,%3};"
        : "+f"(c[0]),"+f"(c[1]),"+f"(c[2]),"+f"(c[3])
        : "r"(a[0]),"r"(a[1]),"r"(a[2]),"r"(a[3]),"r"(b0),"r"(b1));
}
#define INS4(vv, xx, nv, ni) do{ \
  if ((nv) < vv[3]) { \
    if ((nv) < vv[1]) { \
      vv[3]=vv[2]; xx[3]=xx[2]; vv[2]=vv[1]; xx[2]=xx[1]; \
      if ((nv) < vv[0]) { vv[1]=vv[0]; xx[1]=xx[0]; vv[0]=(nv); xx[0]=(ni); } \
      else { vv[1]=(nv); xx[1]=(ni); } \
    } else { \
      if ((nv) < vv[2]) { vv[3]=vv[2]; xx[3]=xx[2]; vv[2]=(nv); xx[2]=(ni); } \
      else { vv[3]=(nv); xx[3]=(ni); } \
    } \
  } }while(0)

__global__ void rvq_prep_kernel(const float* __restrict__ cbs){
    int id = blockIdx.x*blockDim.x + threadIdx.x;
    if (id >= NQ*BINS*DIM) return;
    int d = id & 255, j = (id>>8) & 1023, q = id>>18;
    __half hi = __float2half_rn(cbs[id]);
    int jc = j>>5, jr = j&31;
    uint32_t unit = (uint32_t)(d>>3);
    uint32_t off = (uint32_t)jr*512u + ((unit ^ (uint32_t)(jr&7))<<4) + (uint32_t)(d&7)*2u;
    *(__half*)(g_bimg + (size_t)(q*32+jc)*CHUNK_B + off) = hi;
}

__global__ void rvq_cbsq_kernel(const float* __restrict__ cbs){
    int id = blockIdx.x*blockDim.x + threadIdx.x;
    if (id >= NQ*BINS) return;
    const float* c = cbs + (size_t)id*DIM;
    float s0=0,s1=0,s2=0,s3=0;
    #pragma unroll 8
    for (int d=0; d<DIM; d+=4){
        float4 v = *(const float4*)(c+d);
        s0=fmaf(v.x,v.x,s0); s1=fmaf(v.y,v.y,s1); s2=fmaf(v.z,v.z,s2); s3=fmaf(v.w,v.w,s3);
    }
    float n2 = (s0+s1)+(s2+s3);
    g_cbsq[id] = n2;
    atomicMax(&g_cmaxbits[id>>10], __float_as_int(n2));
}

__global__ __launch_bounds__(256,1)
void rvq_main_kernel(const float* __restrict__ x, const float* __restrict__ cbs,
                     float* __restrict__ out){
    extern __shared__ char smc[];
    const uint32_t sb = smem_u32(smc);
    const int tid = threadIdx.x, l = tid&31, w = tid>>5, bid = blockIdx.x;
    const int b = bid>>5, t0 = (bid&31)<<8;
    const float* xblk = x + ((size_t)b*DIM)*TT + t0;
    float* gres = g_res + ((size_t)bid)*MT*DIM;   // [m][d]
    float* cbsq_s = (float*)(smc+SO_CBSQ);
    int*   sidx   = (int*)(smc+SO_SIDX);
    float* ssqs   = (float*)(smc+SO_SSQ);
    float* rsq    = (float*)(smc+SO_RSQ);
    int*   fcnt   = (int*)(smc+SO_FCNT);
    int*   ftok   = (int*)(smc+SO_FTOK);
    int*   fesc   = (int*)(smc+SO_FESC);
    int*   cand   = (int*)(smc+SO_CAND);
    __half* pH = (__half*)(smc+SO_AHI);
    #define FULLB(i)  (sb+SO_MBAR + (uint32_t)(i)*8u)
    #define EMPTYB(i) (sb+SO_MBAR + 32u + (uint32_t)(i)*8u)

    if (tid==0){
        #pragma unroll
        for (int i=0;i<4;++i){ MBAR_INIT(FULLB(i),1); MBAR_INIT(EMPTYB(i),8); }
    }

    // residual = x: hi fp16 in SMEM, exact fp32 in global scratch
    for (int i=tid; i<DIM*MT; i+=256){
        int d = i>>8, m = i&255;
        float v = xblk[(size_t)d*TT+m];
        pH[m*ASTR_H + d] = __float2half_rn(v);
        gres[(size_t)m*DIM + d] = v;
    }
    __syncthreads();
    if (tid < MT){
        float s = 0.f;
        const float* rr = gres + (size_t)tid*DIM;
        for (int d=0; d<DIM; d+=4){
            float4 v = *(const float4*)(rr+d);
            s = fmaf(v.x,v.x,fmaf(v.y,v.y,fmaf(v.z,v.z,fmaf(v.w,v.w,s))));
        }
        rsq[tid] = s;
    }
    __syncthreads();

    const uint32_t aW0 = sb + SO_AHI + (w*32 + (l&15))*ASTR_B + (l>>4)*16;
    const uint32_t aW1 = aW0 + 16*ASTR_B;
    const int nr  = (l&7) | ((l&16)>>1);
    const int suu = (l>>3)&1;
    const uint32_t xorv = (uint32_t)(nr&7);
    const uint32_t bRow = sb + SO_B + (uint32_t)nr*512u;
    const int grpLead = l & ~3;

    int pf[4] = {0,0,0,0};
    int pe[4] = {1,1,1,1};

    if (tid==0){
        #pragma unroll
        for (int p=0; p<3; ++p){
            mbar_wait(EMPTYB(p), pe[p]); pe[p]^=1;
            MBAR_EXPECT_TX(FULLB(p), CHUNK_B);
            bulkcp(sb+SO_B+(uint32_t)p*CHUNK_B, g_bimg + (size_t)p*CHUNK_B, CHUNK_B, FULLB(p));
        }
    }

    for (int q=0; q<NQ; ++q){
        const float* cbq = cbs + (size_t)q*BINS*DIM;
        for (int i=tid; i<BINS; i+=256) cbsq_s[i] = g_cbsq[q*BINS+i];
        if (tid==0) fcnt[0] = 0;
        const float CE = 1.96e-3f * sqrtf(__int_as_float(g_cmaxbits[q]));
        __syncthreads();

        float vv[4][4]; int xx[4][4];
        #pragma unroll
        for (int s2=0;s2<4;++s2)
            #pragma unroll
            for (int k=0;k<4;++k){ vv[s2][k]=3.4e38f; xx[s2][k]=0; }

        for (int c=0; c<32; ++c){
            const int G = q*32 + c;
            if (tid==0 && G+3 < NCHUNKS){
                const int s3 = (G+3)&3;
                mbar_wait(EMPTYB(s3), pe[s3]); pe[s3]^=1;
                MBAR_EXPECT_TX(FULLB(s3), CHUNK_B);
                bulkcp(sb+SO_B+(uint32_t)s3*CHUNK_B,
                       g_bimg + (size_t)(G+3)*CHUNK_B, CHUNK_B, FULLB(s3));
            }
            const int s = G&3;
            mbar_wait(FULLB(s), pf[s]); pf[s]^=1;

            float acc[2][4][4];
            #pragma unroll
            for (int ti=0;ti<2;++ti)
                #pragma unroll
                for (int t=0;t<4;++t)
                    #pragma unroll
                    for (int i=0;i<4;++i) acc[ti][t][i]=0.f;

            const uint32_t bbase = bRow + (uint32_t)s*CHUNK_B;
            #pragma unroll 4
            for (int kt=0; kt<16; ++kt){
                uint32_t a0[4], a1[4];
                ldsm4(a0, aW0 + kt*32);
                ldsm4(a1, aW1 + kt*32);
                const uint32_t cbyte = ((((uint32_t)(kt*2+suu)) ^ xorv) << 4);
                #pragma unroll
                for (int g=0; g<2; ++g){
                    uint32_t bh[4];
                    ldsm4(bh, bbase + (uint32_t)g*8192u + cbyte);
                    mma16816(acc[0][g*2],   a0, bh[0], bh[1]);
                    mma16816(acc[0][g*2+1], a0, bh[2], bh[3]);
                    mma16816(acc[1][g*2],   a1, bh[0], bh[1]);
                    mma16816(acc[1][g*2+1], a1, bh[2], bh[3]);
                }
            }
            if (l==0) MBAR_ARRIVE(EMPTYB(s));

            #pragma unroll
            for (int ti=0;ti<2;++ti){
                #pragma unroll
                for (int t=0;t<4;++t){
                    int n = c*32 + t*8 + (l&3)*2;
                    float d0 = cbsq_s[n]   - 2.f*acc[ti][t][0];
                    float d1 = cbsq_s[n+1] - 2.f*acc[ti][t][1];
                    float d2 = cbsq_s[n]   - 2.f*acc[ti][t][2];
                    float d3 = cbsq_s[n+1] - 2.f*acc[ti][t][3];
                    INS4(vv[ti*2],   xx[ti*2],   d0, n); INS4(vv[ti*2],   xx[ti*2],   d1, n+1);
                    INS4(vv[ti*2+1], xx[ti*2+1], d2, n); INS4(vv[ti*2+1], xx[ti*2+1], d3, n+1);
                }
            }
        }

        #pragma unroll
        for (int slot=0; slot<4; ++slot){
            float* sv = vv[slot]; int* sx = xx[slot];
            float b1v = sv[0], b2v = sv[1];
            int   b1i = sx[0];
            #pragma unroll
            for (int off=1; off<=2; off<<=1){
                float o1v = __shfl_xor_sync(0xFFFFFFFFu, b1v, off);
                int   o1i = __shfl_xor_sync(0xFFFFFFFFu, b1i, off);
                float o2v = __shfl_xor_sync(0xFFFFFFFFu, b2v, off);
                if (o1v < b1v || (o1v == b1v && o1i < b1i)){
                    b2v = fminf(b1v, o2v); b1v = o1v; b1i = o1i;
                } else b2v = fminf(b2v, o1v);
            }
            int m = w*32 + (slot>>1)*16 + (l>>2) + (slot&1)*8;
            float E = CE * sqrtf(fmaxf(rsq[m], 0.f));
            float epsw = 2.1f*E + 0.02f;
            float W = b1v + epsw;
            bool flag = (b2v <= W);
            int fi = -1;
            if (flag && (l&3)==0) fi = atomicAdd(fcnt, 1);
            fi = __shfl_sync(0xFFFFFFFFu, fi, grpLead);
            int escb = (sv[3] <= W) ? 1 : 0;
            escb |= __shfl_xor_sync(0xFFFFFFFFu, escb, 1);
            escb |= __shfl_xor_sync(0xFFFFFFFFu, escb, 2);
            if (flag){
                if ((l&3)==0){ ftok[fi] = m; fesc[fi] = escb; }
                #pragma unroll
                for (int k=0;k<3;++k)
                    cand[fi*12 + (l&3)*3 + k] = (sv[k] <= W) ? sx[k] : -1;
            } else if ((l&3)==0){
                sidx[m] = b1i;
                out[QOFF + ((size_t)(q*BB+b))*TT + t0 + m] = (float)b1i;
                rsq[m] = fmaxf(rsq[m] + b1v + epsw, 0.f);
            }
        }
        __syncthreads();

        {
            const int nf = fcnt[0];
            for (int f = w; f < nf; f += 8){
                int m = ftok[f], esc = fesc[f];
                float rv[8];
                const float* rr = gres + (size_t)m*DIM + l*8;
                float4 r4a = *(const float4*)(rr), r4b = *(const float4*)(rr+4);
                rv[0]=r4a.x; rv[1]=r4a.y; rv[2]=r4a.z; rv[3]=r4a.w;
                rv[4]=r4b.x; rv[5]=r4b.y; rv[6]=r4b.z; rv[7]=r4b.w;
                float be = 3.4e38f; int bj = 0;
                if (!esc){
                    for (int k=0; k<12; ++k){
                        int j = cand[f*12+k];
                        if (j < 0) continue;
                        const float4* cr = (const float4*)(cbq + (size_t)j*DIM + l*8);
                        float4 ca = cr[0], cb2 = cr[1];
                        float s = rv[0]*ca.x + rv[1]*ca.y + rv[2]*ca.z + rv[3]*ca.w
                                + rv[4]*cb2.x + rv[5]*cb2.y + rv[6]*cb2.z + rv[7]*cb2.w;
                        #pragma unroll
                        for (int off2=16; off2>0; off2>>=1) s += __shfl_xor_sync(0xFFFFFFFFu, s, off2);
                        float e2 = cbsq_s[j] - 2.f*s;
                        if (e2 < be || (e2 == be && j < bj)){ be = e2; bj = j; }
                    }
                } else {
                    for (int j=0; j<BINS; ++j){
                        const float4* cr = (const float4*)(cbq + (size_t)j*DIM + l*8);
                        float4 ca = cr[0], cb2 = cr[1];
                        float s = rv[0]*ca.x + rv[1]*ca.y + rv[2]*ca.z + rv[3]*ca.w
                                + rv[4]*cb2.x + rv[5]*cb2.y + rv[6]*cb2.z + rv[7]*cb2.w;
                        #pragma unroll
                        for (int off2=16; off2>0; off2>>=1) s += __shfl_xor_sync(0xFFFFFFFFu, s, off2);
                        float e2 = cbsq_s[j] - 2.f*s;
                        if (e2 < be){ be = e2; bj = j; }
                    }
                }
                if (l==0){
                    sidx[m] = bj;
                    out[QOFF + ((size_t)(q*BB+b))*TT + t0 + m] = (float)bj;
                    rsq[m] = fmaxf(rsq[m] + be + 0.05f, 0.f);
                }
            }
        }
        __syncthreads();

        {   // residual update, tid = dim d; exact fp32 in gres, hi to SMEM
            float ssq = 0.f;
            #pragma unroll 4
            for (int m=0; m<MT; ++m){
                int ix = sidx[m];
                float cv = __ldg(cbq + (size_t)ix*DIM + tid);
                float r = gres[(size_t)m*DIM + tid];
                float rn = r - cv;
                gres[(size_t)m*DIM + tid] = rn;
                pH[m*ASTR_H + tid] = __float2half_rn(rn);
                ssq = fmaf(rn, rn, ssq);
            }
            #pragma unroll
            for (int o2=16;o2>0;o2>>=1) ssq += __shfl_xor_sync(0xFFFFFFFFu, ssq, o2);
            if (l==0) ssqs[w] = ssq;
            __syncthreads();
            if (tid==0){
                float sacc=0.f;
                #pragma unroll
                for (int ww=0; ww<8; ++ww) sacc += ssqs[ww];
                g_ssq[q*NBLK+bid] = sacc;
            }
            __syncthreads();
        }
    }

    for (int i=tid; i<DIM*MT; i+=256){
        int d = i>>8, m = i&255;
        out[((size_t)b*DIM+d)*TT + t0 + m] =
            xblk[(size_t)d*TT+m] - gres[(size_t)m*DIM + d];
    }
}

__global__ void rvq_finalize_kernel(const int* __restrict__ sr_raw, float* __restrict__ out){
    __shared__ float red[8];
    const int tid = threadIdx.x;
    float s = 0.f;
    #pragma unroll
    for (int i=0; i<NQ*NBLK/256; ++i) s += g_ssq[tid + i*256];
    #pragma unroll
    for (int o=16;o>0;o>>=1) s += __shfl_xor_sync(0xFFFFFFFFu, s, o);
    if ((tid&31)==0) red[tid>>5] = s;
    __syncthreads();
    if (tid==0){
        float tot=0.f;
        #pragma unroll
        for (int w=0; w<8; ++w) tot += red[w];
        int iv = sr_raw[0];
        float sr = (iv > 0 && iv < 100000000) ? (float)iv : __int_as_float(iv);
        out[COFF+0] = (float)NQ * 10.0f * (sr / 1000.0f);
        out[COFF+1] = tot * (0.25f / ((float)((size_t)NTOK*DIM))) / (float)NQ;
    }
}

extern "C" void kernel_launch(void* const* d_in, const int* in_sizes, int n_in,
                              void* d_out, int out_size){
    const float* x   = (const float*)d_in[0];
    const int*   sr  = (const int*)d_in[1];
    const float* cbs = (const float*)d_in[2];
    float* out = (float*)d_out;
    cudaFuncSetAttribute(rvq_main_kernel, cudaFuncAttributeMaxDynamicSharedMemorySize, SMEM_BYTES);
    rvq_prep_kernel<<<(NQ*BINS*DIM+255)/256, 256>>>(cbs);
    rvq_cbsq_kernel<<<(NQ*BINS+255)/256, 256>>>(cbs);
    rvq_main_kernel<<<NBLK, 256, SMEM_BYTES>>>(x, cbs, out);
    rvq_finalize_kernel<<<1, 256>>>(sr, out);
}